// round 10
// baseline (speedup 1.0000x reference)
#include <cuda_runtime.h>
#include <cstdint>
#include <math.h>

// Problem constants
#define S_TOK 8192
#define MDIM  4096
#define NEXP  64
#define CAP   128
#define SEC   67108864ULL            // S*E*C
#define OUT_FLOATS 134217793ULL      // 1 + 2*SEC + 64
#define ZMAIN 134217728ULL           // floats zeroed by bulk path (512MB)

// GEMM tiling (R6 proven config)
#define TILE_M 256                   // tokens per CTA
#define KB     16
#define KSPLIT 4
#define KCHUNK (MDIM / KSPLIT)       // 1024
#define NSTEP  (KCHUNK / KB)         // 64
#define NTB    (S_TOK / TILE_M)      // 32 token blocks
#define NCOMP  (NTB * KSPLIT)        // 128 compute CTAs
#define NZC    16                    // dedicated zero CTAs
#define GRID_G (NCOMP + NZC)         // 144 CTAs, one wave on 148 SMs
#define THREADS 256
#define LDA 260                      // A smem row stride (floats)
#define LDB 68                       // B smem row stride (floats)

#define ZCHUNK 16384                 // bytes per bulk store
#define ZPW    256                   // chunks per warp-leader (8 warps/CTA)
#define ZPC    (8 * ZPW)             // 2048 chunks per zero CTA = 32MB

#define NBLK64 (S_TOK / 64)          // 128 blocks for gate/scatter

typedef unsigned long long u64;

// ---------- scratch (device globals; fully overwritten each launch) ----------
__device__ float g_part[KSPLIT * S_TOK * NEXP];   // 8 MB partial logits
__device__ int   g_eid[S_TOK];
__device__ float g_gate[S_TOK];
__device__ float g_me[NBLK64 * NEXP];
__device__ int   g_cnt[NBLK64 * NEXP];

// packed f32x2 FMA (PTX-only; ptxas never auto-fuses)
__device__ __forceinline__ void ffma2(u64& d, u64 a, u64 b) {
    asm("fma.rn.f32x2 %0, %1, %2, %0;" : "+l"(d) : "l"(a), "l"(b));
}
__device__ __forceinline__ u64 dup2(float b) {
    u64 r; unsigned u = __float_as_uint(b);
    asm("mov.b64 %0, {%1, %1};" : "=l"(r) : "r"(u));
    return r;
}
__device__ __forceinline__ uint32_t smem_u32(const void* p) {
    uint32_t a;
    asm("{ .reg .u64 t; cvta.to.shared.u64 t, %1; cvt.u32.u64 %0, t; }"
        : "=r"(a) : "l"(p));
    return a;
}

// ---------------------------------------------------------------------------
// Kernel 1: SM-specialized grid. CTAs 0-127: 256x64 fp32 GEMM over a K/4
// chunk (R6 shape: per-thread 8 tok x 8 exp, 32 FFMA2 / 4 LDS.128 per kk,
// double buffer). CTAs 128-143: pure TMA bulk-zero of the 537MB output
// (32MB each, 8 warp-leaders x 256 x 16KB chunks).
// ---------------------------------------------------------------------------
__global__ __launch_bounds__(THREADS, 1) void gemm_zero_kernel(
    const float* __restrict__ x, const float* __restrict__ wg,
    float* __restrict__ out)
{
    __shared__ float sA[2][KB * LDA];                 // 2 x 16.25 KB
    __shared__ float sB[2][KB * LDB];                 // 2 x 4.25 KB
    __shared__ alignas(16) float4 zbuf[ZCHUNK / 16];  // 16 KB zeros

    const int t  = threadIdx.x;
    const int bx = blockIdx.x;

    if (bx >= NCOMP) {
        // ---------------- dedicated zero CTA ----------------
        const int z = bx - NCOMP;              // 0..15
        {
            const float4 zv = make_float4(0.f, 0.f, 0.f, 0.f);
            for (int i = t; i < ZCHUNK / 16; i += THREADS) zbuf[i] = zv;
        }
        __syncthreads();
        asm volatile("fence.proxy.async.shared::cta;" ::: "memory");
        const int w    = t >> 5;
        const int lane = t & 31;
        if (lane == 0) {
            const uint32_t zaddr = smem_u32(zbuf);
            char* dst = (char*)out
                      + ((size_t)z * ZPC + (size_t)w * ZPW) * (size_t)ZCHUNK;
            #pragma unroll 4
            for (int c = 0; c < ZPW; c++) {
                asm volatile(
                    "cp.async.bulk.global.shared::cta.bulk_group [%0], [%1], %2;"
                    :: "l"(dst + (size_t)c * ZCHUNK), "r"(zaddr), "r"(ZCHUNK)
                    : "memory");
            }
            asm volatile("cp.async.bulk.commit_group;" ::: "memory");
            asm volatile("cp.async.bulk.wait_group 0;" ::: "memory");
        }
        // tail: last 65 floats
        if (z == 0 && t < (int)(OUT_FLOATS - ZMAIN))
            out[ZMAIN + t] = 0.0f;
        return;
    }

    // ---------------- compute CTA (R6 config) ----------------
    const int tb = bx & (NTB - 1);     // token block (0..31)
    const int kh = bx >> 5;            // k chunk (0..3)
    const int w    = t >> 5;           // warp 0..7
    const int lane = t & 31;
    const int tb2  = w >> 1;           // warp token sub-block (0..3): 64 tokens
    const int eb   = w & 1;            // warp expert half (0..1): 32 experts
    const int tg   = lane >> 2;        // token group (0..7): 8 tokens
    const int eg   = lane & 3;         // expert group (0..3): 8 experts
    const int tok0 = tb2 * 64 + tg * 8;
    const int e0   = eb * 32 + eg * 8;

    u64 acc[4][8];                     // 4 token-pairs x 8 experts
    #pragma unroll
    for (int p = 0; p < 4; p++)
        #pragma unroll
        for (int j = 0; j < 8; j++) acc[p][j] = 0ULL;

    const float* xblk = x  + (size_t)tb * TILE_M * MDIM + (size_t)kh * KCHUNK;
    const float* wblk = wg + (size_t)kh * KCHUNK;

    const int arow = t >> 2;           // 0..63
    const int akq  = t & 3;            // 0..3
    const int brow = t >> 2;           // 0..63 (expert)
    const int bkq  = t & 3;            // 0..3

    float4 pa[4]; float4 pb;
    #pragma unroll
    for (int i = 0; i < 4; i++)
        pa[i] = *(const float4*)(xblk + (size_t)(arow + i * 64) * MDIM + akq * 4);
    pb = *(const float4*)(wblk + (size_t)brow * MDIM + bkq * 4);

    // stage step 0
    #pragma unroll
    for (int i = 0; i < 4; i++) {
        const int r = arow + i * 64;
        sA[0][(akq * 4 + 0) * LDA + r] = pa[i].x;
        sA[0][(akq * 4 + 1) * LDA + r] = pa[i].y;
        sA[0][(akq * 4 + 2) * LDA + r] = pa[i].z;
        sA[0][(akq * 4 + 3) * LDA + r] = pa[i].w;
    }
    sB[0][(bkq * 4 + 0) * LDB + brow] = pb.x;
    sB[0][(bkq * 4 + 1) * LDB + brow] = pb.y;
    sB[0][(bkq * 4 + 2) * LDB + brow] = pb.z;
    sB[0][(bkq * 4 + 3) * LDB + brow] = pb.w;
    __syncthreads();

    #pragma unroll 1
    for (int s = 0; s < NSTEP; s++) {
        const int cur = s & 1;

        if (s + 1 < NSTEP) {           // prefetch next step
            const int k1 = (s + 1) * KB;
            #pragma unroll
            for (int i = 0; i < 4; i++)
                pa[i] = *(const float4*)(xblk + (size_t)(arow + i * 64) * MDIM + k1 + akq * 4);
            pb = *(const float4*)(wblk + (size_t)brow * MDIM + k1 + bkq * 4);
        }

        #pragma unroll
        for (int kk = 0; kk < KB; kk++) {
            const float* ap = &sA[cur][kk * LDA + tok0];
            ulonglong2 a01 = *(const ulonglong2*)(ap);
            ulonglong2 a23 = *(const ulonglong2*)(ap + 4);
            float4 b03 = *(const float4*)&sB[cur][kk * LDB + e0];
            float4 b47 = *(const float4*)&sB[cur][kk * LDB + e0 + 4];
            u64 ar[4] = { a01.x, a01.y, a23.x, a23.y };
            u64 bd[8] = { dup2(b03.x), dup2(b03.y), dup2(b03.z), dup2(b03.w),
                          dup2(b47.x), dup2(b47.y), dup2(b47.z), dup2(b47.w) };
            #pragma unroll
            for (int p = 0; p < 4; p++)
                #pragma unroll
                for (int j = 0; j < 8; j++)
                    ffma2(acc[p][j], ar[p], bd[j]);
        }

        if (s + 1 < NSTEP) {           // stage next step into other buffer
            const int nxt = cur ^ 1;
            #pragma unroll
            for (int i = 0; i < 4; i++) {
                const int r = arow + i * 64;
                sA[nxt][(akq * 4 + 0) * LDA + r] = pa[i].x;
                sA[nxt][(akq * 4 + 1) * LDA + r] = pa[i].y;
                sA[nxt][(akq * 4 + 2) * LDA + r] = pa[i].z;
                sA[nxt][(akq * 4 + 3) * LDA + r] = pa[i].w;
            }
            sB[nxt][(bkq * 4 + 0) * LDB + brow] = pb.x;
            sB[nxt][(bkq * 4 + 1) * LDB + brow] = pb.y;
            sB[nxt][(bkq * 4 + 2) * LDB + brow] = pb.z;
            sB[nxt][(bkq * 4 + 3) * LDB + brow] = pb.w;
        }
        __syncthreads();
    }

    // epilogue: write partial logits [kh][token][expert]
    float* part = g_part + (size_t)kh * S_TOK * NEXP;
    #pragma unroll
    for (int p = 0; p < 4; p++) {
        const size_t t0 = (size_t)tb * TILE_M + tok0 + p * 2;
        float4 lo0, lo1, hi0, hi1;
        lo0.x = __uint_as_float((unsigned)acc[p][0]);
        lo0.y = __uint_as_float((unsigned)acc[p][1]);
        lo0.z = __uint_as_float((unsigned)acc[p][2]);
        lo0.w = __uint_as_float((unsigned)acc[p][3]);
        lo1.x = __uint_as_float((unsigned)acc[p][4]);
        lo1.y = __uint_as_float((unsigned)acc[p][5]);
        lo1.z = __uint_as_float((unsigned)acc[p][6]);
        lo1.w = __uint_as_float((unsigned)acc[p][7]);
        hi0.x = __uint_as_float((unsigned)(acc[p][0] >> 32));
        hi0.y = __uint_as_float((unsigned)(acc[p][1] >> 32));
        hi0.z = __uint_as_float((unsigned)(acc[p][2] >> 32));
        hi0.w = __uint_as_float((unsigned)(acc[p][3] >> 32));
        hi1.x = __uint_as_float((unsigned)(acc[p][4] >> 32));
        hi1.y = __uint_as_float((unsigned)(acc[p][5] >> 32));
        hi1.z = __uint_as_float((unsigned)(acc[p][6] >> 32));
        hi1.w = __uint_as_float((unsigned)(acc[p][7] >> 32));
        *(float4*)&part[t0 * NEXP + e0 + 0]       = lo0;
        *(float4*)&part[t0 * NEXP + e0 + 4]       = lo1;
        *(float4*)&part[(t0 + 1) * NEXP + e0 + 0] = hi0;
        *(float4*)&part[(t0 + 1) * NEXP + e0 + 4] = hi1;
    }
}

// ---------------------------------------------------------------------------
// Kernel 2 (R6): reduce K-split partials, softmax/argmax, per-block me/cnt.
// ---------------------------------------------------------------------------
__global__ __launch_bounds__(256) void gate_kernel()
{
    __shared__ float Ls[64 * 65];
    __shared__ int   s_eid[64];
    const int b = blockIdx.x;        // 0..127
    const int t = threadIdx.x;
    const size_t off = (size_t)b * 64 * NEXP;

    #pragma unroll
    for (int i = 0; i < 4; i++) {
        const int idx4 = t + i * 256;     // 0..1023
        float4 v = *(const float4*)&g_part[off + (size_t)idx4 * 4];
        #pragma unroll
        for (int p = 1; p < KSPLIT; p++) {
            float4 w = *(const float4*)&g_part[(size_t)p * S_TOK * NEXP + off + (size_t)idx4 * 4];
            v.x += w.x; v.y += w.y; v.z += w.z; v.w += w.w;
        }
        const int r = (idx4 * 4) >> 6;
        const int e = (idx4 * 4) & 63;
        Ls[r * 65 + e + 0] = v.x;
        Ls[r * 65 + e + 1] = v.y;
        Ls[r * 65 + e + 2] = v.z;
        Ls[r * 65 + e + 3] = v.w;
    }
    __syncthreads();

    if (t < 64) {
        const int r = t;
        float m = -INFINITY; int am = 0;
        #pragma unroll 8
        for (int e = 0; e < NEXP; e++) {
            float v = Ls[r * 65 + e];
            if (v > m) { m = v; am = e; }
        }
        float sum = 0.f;
        #pragma unroll 8
        for (int e = 0; e < NEXP; e++) {
            float ex = expf(Ls[r * 65 + e] - m);
            Ls[r * 65 + e] = ex;
            sum += ex;
        }
        const float inv = 1.f / sum;
        #pragma unroll 8
        for (int e = 0; e < NEXP; e++) Ls[r * 65 + e] *= inv;
        const int s = b * 64 + r;
        g_eid[s]  = am;
        g_gate[s] = inv;
        s_eid[r]  = am;
    }
    __syncthreads();

    if (t < NEXP) {
        const int e = t;
        float msum = 0.f; int cnt = 0;
        #pragma unroll 8
        for (int r = 0; r < 64; r++) {
            msum += Ls[r * 65 + e];
            cnt  += (s_eid[r] == e);
        }
        g_me[b * NEXP + e]  = msum;
        g_cnt[b * NEXP + e] = cnt;
    }
}

// ---------------------------------------------------------------------------
// Kernel 3 (R9): scatter with vectorized staging and 4-way-parallel offset
// prefix. 256 threads. Block 0: exp_counts + l_aux.
// ---------------------------------------------------------------------------
__global__ __launch_bounds__(256) void scatter_kernel(float* __restrict__ out)
{
    __shared__ int   sc[NBLK64 * NEXP];   // 32 KB staged counts
    __shared__ int   s_part[4][64];
    __shared__ int   s_e[64];
    __shared__ float s_g[64];
    __shared__ int   cnt0[NEXP];
    __shared__ float s_val[NEXP];

    const int b = blockIdx.x;
    const int t = threadIdx.x;            // 0..255

    // stage counts: 2048 int4 by 256 threads = 8 LDG.128 each (full MLP)
    {
        const int4* g4 = (const int4*)g_cnt;
        int4* s4 = (int4*)sc;
        #pragma unroll
        for (int j = 0; j < 8; j++) s4[t + j * 256] = g4[t + j * 256];
    }
    if (t < 64) {
        s_e[t]  = g_eid[b * 64 + t];
        s_g[t]  = g_gate[b * 64 + t];
        cnt0[t] = 0;
    }
    __syncthreads();

    // 4-way parallel offset prefix: thread (q, tok) sums cnt[q*32 .. ) ∩ [0,b)
    {
        const int tok = t & 63;
        const int q   = t >> 6;           // 0..3
        const int e   = s_e[tok];
        const int lo  = q * 32;
        const int hi  = (b < lo + 32) ? b : (lo + 32);
        int sum = 0;
        #pragma unroll 8
        for (int bp = lo; bp < hi; bp++) sum += sc[bp * NEXP + e];
        s_part[q][tok] = sum;
    }
    __syncthreads();

    // rank + scatter (first two warps; one token each)
    int ee = 0, rank_w = 0, offs = 0; float gg = 0.f; unsigned mm = 0;
    if (t < 64) {
        ee   = s_e[t];
        gg   = s_g[t];
        offs = s_part[0][t] + s_part[1][t] + s_part[2][t] + s_part[3][t];
        mm   = __match_any_sync(0xFFFFFFFFu, ee);
        const int lane = t & 31;
        rank_w = __popc(mm & ((1u << lane) - 1u));
        if (t < 32 && lane == __ffs(mm) - 1) cnt0[ee] = __popc(mm);
    }
    __syncthreads();
    if (t >= 32 && t < 64) rank_w += cnt0[ee];
    if (t < 64) {
        const int rank = offs + rank_w;
        if (rank < CAP) {
            const int s = b * 64 + t;
            size_t base = (size_t)s * (NEXP * CAP) + (size_t)ee * CAP + rank;
            out[1 + base]       = gg;     // combine_weights
            out[1 + SEC + base] = 1.0f;   // dispatch_mask
        }
    }

    // block 0: exp_counts + l_aux from staged counts
    if (b == 0) {
        __syncthreads();
        {
            const int ex = t & 63;
            const int q  = t >> 6;
            int sum = 0;
            #pragma unroll 8
            for (int bp = q * 32; bp < q * 32 + 32; bp++) sum += sc[bp * NEXP + ex];
            s_part[q][ex] = sum;
        }
        __syncthreads();
        if (t < 64) {
            const int run = s_part[0][t] + s_part[1][t] + s_part[2][t] + s_part[3][t];
            float me_tot = 0.f;
            #pragma unroll 8
            for (int bp = 0; bp < NBLK64; bp++) me_tot += g_me[bp * NEXP + t];
            out[1 + 2 * SEC + t] = (float)run;     // exp_counts (pre-drop)
            s_val[t] = me_tot * (float)run;
        }
        __syncthreads();
        if (t == 0) {
            float acc = 0.f;
            for (int k = 0; k < NEXP; k++) acc += s_val[k];
            out[0] = acc * (1.f / 1048576.f);      // E/S^2 = 64/8192^2
        }
    }
}

// ---------------------------------------------------------------------------
extern "C" void kernel_launch(void* const* d_in, const int* in_sizes, int n_in,
                              void* d_out, int out_size)
{
    const float* x  = (const float*)d_in[0];
    const float* wg = (const float*)d_in[1];
    float* out = (float*)d_out;

    gemm_zero_kernel<<<GRID_G, THREADS>>>(x, wg, out);
    gate_kernel<<<NBLK64, 256>>>();
    scatter_kernel<<<NBLK64, 256>>>(out);
}

// round 11
// speedup vs baseline: 2.4645x; 2.4645x over previous
#include <cuda_runtime.h>
#include <cstdint>
#include <math.h>

// Problem constants
#define S_TOK 8192
#define MDIM  4096
#define NEXP  64
#define CAP   128
#define SEC   67108864ULL            // S*E*C
#define OUT_FLOATS 134217793ULL      // 1 + 2*SEC + 64
#define ZMAIN 134217728ULL           // floats zeroed by bulk path (512MB)

// GEMM tiling (R6/R9 proven config)
#define TILE_M 256                   // tokens per CTA
#define KB     16
#define KSPLIT 4
#define KCHUNK (MDIM / KSPLIT)       // 1024
#define NSTEP  (KCHUNK / KB)         // 64
#define NTB    (S_TOK / TILE_M)      // 32 token blocks
#define GRID_G (NTB * KSPLIT)        // 128 CTAs (1 per SM)
#define CTHR   256                   // compute threads (8 warps)
#define THREADS (CTHR + 32)          // + 1 TMA-zero warp
#define LDA 260                      // A smem row stride (floats)
#define LDBD 66                      // B-dup smem row stride (u64), 528B

#define ZCHUNK 4096                  // bytes per bulk store
#define ZPC    1024                  // chunks per CTA (128*1024*4KB = 512MB)

#define NBLK64 (S_TOK / 64)          // 128 blocks for gate/scatter

typedef unsigned long long u64;

// ---------- scratch (device globals; fully overwritten each launch) ----------
__device__ float g_part[KSPLIT * S_TOK * NEXP];   // 8 MB partial logits
__device__ int   g_eid[S_TOK];
__device__ float g_gate[S_TOK];
__device__ float g_me[NBLK64 * NEXP];
__device__ int   g_cnt[NBLK64 * NEXP];

// packed f32x2 FMA (PTX-only; ptxas never auto-fuses)
__device__ __forceinline__ void ffma2(u64& d, u64 a, u64 b) {
    asm("fma.rn.f32x2 %0, %1, %2, %0;" : "+l"(d) : "l"(a), "l"(b));
}
__device__ __forceinline__ u64 dup2(float b) {
    u64 r; unsigned u = __float_as_uint(b);
    asm("mov.b64 %0, {%1, %1};" : "=l"(r) : "r"(u));
    return r;
}
__device__ __forceinline__ void barc() {   // compute-warps-only barrier
    asm volatile("bar.sync 1, %0;" :: "n"(CTHR) : "memory");
}
__device__ __forceinline__ uint32_t smem_u32(const void* p) {
    uint32_t a;
    asm("{ .reg .u64 t; cvta.to.shared.u64 t, %1; cvt.u32.u64 %0, t; }"
        : "=r"(a) : "l"(p));
    return a;
}

// ---------------------------------------------------------------------------
// Kernel 1: warps 0-7 = 256x64 fp32 GEMM over a K/4 chunk (per-thread
// 8 tok x 8 exp; B pre-duplicated at staging so the inner loop is
// 2 A-LDS.128 + 4 B-LDS.128 + 32 FFMA2). Double buffer, one barrier/step.
// Warp 8 = TMA bulk-zero of the 537MB output (R9 proven engine).
// ---------------------------------------------------------------------------
__global__ __launch_bounds__(THREADS, 1) void gemm_zero_kernel(
    const float* __restrict__ x, const float* __restrict__ wg,
    float* __restrict__ out)
{
    __shared__ float sA[2][KB * LDA];                 // 2 x 16.25 KB
    __shared__ u64   sBd[2][KB * LDBD];               // 2 x 8.25 KB (dup B)
    __shared__ alignas(16) float4 zbuf[ZCHUNK / 16];  // 4 KB zeros

    const int t  = threadIdx.x;
    const int bx = blockIdx.x;

    {
        const float4 z = make_float4(0.f, 0.f, 0.f, 0.f);
        for (int i = t; i < ZCHUNK / 16; i += THREADS) zbuf[i] = z;
    }
    __syncthreads();

    if (t >= CTHR) {
        // ---------------- TMA zero warp ----------------
        const int zt = t - CTHR;
        if (zt == 0) {
            asm volatile("fence.proxy.async.shared::cta;" ::: "memory");
            const uint32_t zaddr = smem_u32(zbuf);
            char* dst = (char*)out + (size_t)bx * (ZPC * (size_t)ZCHUNK);
            #pragma unroll 4
            for (int c = 0; c < ZPC; c++) {
                asm volatile(
                    "cp.async.bulk.global.shared::cta.bulk_group [%0], [%1], %2;"
                    :: "l"(dst + (size_t)c * ZCHUNK), "r"(zaddr), "r"(ZCHUNK)
                    : "memory");
            }
            asm volatile("cp.async.bulk.commit_group;" ::: "memory");
            asm volatile("cp.async.bulk.wait_group 0;" ::: "memory");
        }
        if (bx == 0) {   // tail: last 65 floats
            for (int i = zt; i < (int)(OUT_FLOATS - ZMAIN); i += 32)
                out[ZMAIN + i] = 0.0f;
        }
        return;
    }

    // ---------------- compute warps ----------------
    const int tb = bx & (NTB - 1);     // token block (0..31)
    const int kh = bx >> 5;            // k chunk (0..3)
    const int w    = t >> 5;           // warp 0..7
    const int lane = t & 31;
    const int tb2  = w >> 1;           // warp token sub-block (0..3): 64 tokens
    const int eb   = w & 1;            // warp expert half (0..1): 32 experts
    const int tg   = lane >> 2;        // token group (0..7): 8 tokens
    const int eg   = lane & 3;         // expert group (0..3): 8 experts
    const int tok0 = tb2 * 64 + tg * 8;
    const int e0   = eb * 32 + eg * 8; // u64 units in sBd

    u64 acc[4][8];                     // 4 token-pairs x 8 experts
    #pragma unroll
    for (int p = 0; p < 4; p++)
        #pragma unroll
        for (int j = 0; j < 8; j++) acc[p][j] = 0ULL;

    const float* xblk = x  + (size_t)tb * TILE_M * MDIM + (size_t)kh * KCHUNK;
    const float* wblk = wg + (size_t)kh * KCHUNK;

    const int arow = t >> 2;           // 0..63 (A rows arow + i*64)
    const int akq  = t & 3;            // 0..3
    const int brow = t >> 2;           // 0..63 (expert)
    const int bkq  = t & 3;            // 0..3

    float4 pa[4]; float4 pb;
    #pragma unroll
    for (int i = 0; i < 4; i++)
        pa[i] = *(const float4*)(xblk + (size_t)(arow + i * 64) * MDIM + akq * 4);
    pb = *(const float4*)(wblk + (size_t)brow * MDIM + bkq * 4);

    // stage step 0
    #pragma unroll
    for (int i = 0; i < 4; i++) {
        const int r = arow + i * 64;
        sA[0][(akq * 4 + 0) * LDA + r] = pa[i].x;
        sA[0][(akq * 4 + 1) * LDA + r] = pa[i].y;
        sA[0][(akq * 4 + 2) * LDA + r] = pa[i].z;
        sA[0][(akq * 4 + 3) * LDA + r] = pa[i].w;
    }
    sBd[0][(bkq * 4 + 0) * LDBD + brow] = dup2(pb.x);
    sBd[0][(bkq * 4 + 1) * LDBD + brow] = dup2(pb.y);
    sBd[0][(bkq * 4 + 2) * LDBD + brow] = dup2(pb.z);
    sBd[0][(bkq * 4 + 3) * LDBD + brow] = dup2(pb.w);
    barc();

    #pragma unroll 1
    for (int s = 0; s < NSTEP; s++) {
        const int cur = s & 1;

        if (s + 1 < NSTEP) {           // prefetch next step
            const int k1 = (s + 1) * KB;
            #pragma unroll
            for (int i = 0; i < 4; i++)
                pa[i] = *(const float4*)(xblk + (size_t)(arow + i * 64) * MDIM + k1 + akq * 4);
            pb = *(const float4*)(wblk + (size_t)brow * MDIM + k1 + bkq * 4);
        }

        // inner loop: 2 A-LDS.128 + 4 B-LDS.128 + 32 FFMA2 per kk
        #pragma unroll
        for (int kk = 0; kk < KB; kk++) {
            const float* ap = &sA[cur][kk * LDA + tok0];
            ulonglong2 a01 = *(const ulonglong2*)(ap);
            ulonglong2 a23 = *(const ulonglong2*)(ap + 4);
            const u64* bp = &sBd[cur][kk * LDBD + e0];
            ulonglong2 b01 = *(const ulonglong2*)(bp);
            ulonglong2 b23 = *(const ulonglong2*)(bp + 2);
            ulonglong2 b45 = *(const ulonglong2*)(bp + 4);
            ulonglong2 b67 = *(const ulonglong2*)(bp + 6);
            u64 ar[4] = { a01.x, a01.y, a23.x, a23.y };
            u64 bd[8] = { b01.x, b01.y, b23.x, b23.y,
                          b45.x, b45.y, b67.x, b67.y };
            #pragma unroll
            for (int p = 0; p < 4; p++)
                #pragma unroll
                for (int j = 0; j < 8; j++)
                    ffma2(acc[p][j], ar[p], bd[j]);
        }

        if (s + 1 < NSTEP) {           // stage next step into other buffer
            const int nxt = cur ^ 1;
            #pragma unroll
            for (int i = 0; i < 4; i++) {
                const int r = arow + i * 64;
                sA[nxt][(akq * 4 + 0) * LDA + r] = pa[i].x;
                sA[nxt][(akq * 4 + 1) * LDA + r] = pa[i].y;
                sA[nxt][(akq * 4 + 2) * LDA + r] = pa[i].z;
                sA[nxt][(akq * 4 + 3) * LDA + r] = pa[i].w;
            }
            sBd[nxt][(bkq * 4 + 0) * LDBD + brow] = dup2(pb.x);
            sBd[nxt][(bkq * 4 + 1) * LDBD + brow] = dup2(pb.y);
            sBd[nxt][(bkq * 4 + 2) * LDBD + brow] = dup2(pb.z);
            sBd[nxt][(bkq * 4 + 3) * LDBD + brow] = dup2(pb.w);
        }
        barc();
    }

    // epilogue: write partial logits [kh][token][expert]
    float* part = g_part + (size_t)kh * S_TOK * NEXP;
    #pragma unroll
    for (int p = 0; p < 4; p++) {
        const size_t t0 = (size_t)tb * TILE_M + tok0 + p * 2;
        float4 lo0, lo1, hi0, hi1;
        lo0.x = __uint_as_float((unsigned)acc[p][0]);
        lo0.y = __uint_as_float((unsigned)acc[p][1]);
        lo0.z = __uint_as_float((unsigned)acc[p][2]);
        lo0.w = __uint_as_float((unsigned)acc[p][3]);
        lo1.x = __uint_as_float((unsigned)acc[p][4]);
        lo1.y = __uint_as_float((unsigned)acc[p][5]);
        lo1.z = __uint_as_float((unsigned)acc[p][6]);
        lo1.w = __uint_as_float((unsigned)acc[p][7]);
        hi0.x = __uint_as_float((unsigned)(acc[p][0] >> 32));
        hi0.y = __uint_as_float((unsigned)(acc[p][1] >> 32));
        hi0.z = __uint_as_float((unsigned)(acc[p][2] >> 32));
        hi0.w = __uint_as_float((unsigned)(acc[p][3] >> 32));
        hi1.x = __uint_as_float((unsigned)(acc[p][4] >> 32));
        hi1.y = __uint_as_float((unsigned)(acc[p][5] >> 32));
        hi1.z = __uint_as_float((unsigned)(acc[p][6] >> 32));
        hi1.w = __uint_as_float((unsigned)(acc[p][7] >> 32));
        *(float4*)&part[t0 * NEXP + e0 + 0]       = lo0;
        *(float4*)&part[t0 * NEXP + e0 + 4]       = lo1;
        *(float4*)&part[(t0 + 1) * NEXP + e0 + 0] = hi0;
        *(float4*)&part[(t0 + 1) * NEXP + e0 + 4] = hi1;
    }
}

// ---------------------------------------------------------------------------
// Kernel 2 (R6): reduce K-split partials, softmax/argmax, per-block me/cnt.
// ---------------------------------------------------------------------------
__global__ __launch_bounds__(256) void gate_kernel()
{
    __shared__ float Ls[64 * 65];
    __shared__ int   s_eid[64];
    const int b = blockIdx.x;        // 0..127
    const int t = threadIdx.x;
    const size_t off = (size_t)b * 64 * NEXP;

    #pragma unroll
    for (int i = 0; i < 4; i++) {
        const int idx4 = t + i * 256;     // 0..1023
        float4 v = *(const float4*)&g_part[off + (size_t)idx4 * 4];
        #pragma unroll
        for (int p = 1; p < KSPLIT; p++) {
            float4 w = *(const float4*)&g_part[(size_t)p * S_TOK * NEXP + off + (size_t)idx4 * 4];
            v.x += w.x; v.y += w.y; v.z += w.z; v.w += w.w;
        }
        const int r = (idx4 * 4) >> 6;
        const int e = (idx4 * 4) & 63;
        Ls[r * 65 + e + 0] = v.x;
        Ls[r * 65 + e + 1] = v.y;
        Ls[r * 65 + e + 2] = v.z;
        Ls[r * 65 + e + 3] = v.w;
    }
    __syncthreads();

    if (t < 64) {
        const int r = t;
        float m = -INFINITY; int am = 0;
        #pragma unroll 8
        for (int e = 0; e < NEXP; e++) {
            float v = Ls[r * 65 + e];
            if (v > m) { m = v; am = e; }
        }
        float sum = 0.f;
        #pragma unroll 8
        for (int e = 0; e < NEXP; e++) {
            float ex = expf(Ls[r * 65 + e] - m);
            Ls[r * 65 + e] = ex;
            sum += ex;
        }
        const float inv = 1.f / sum;
        #pragma unroll 8
        for (int e = 0; e < NEXP; e++) Ls[r * 65 + e] *= inv;
        const int s = b * 64 + r;
        g_eid[s]  = am;
        g_gate[s] = inv;
        s_eid[r]  = am;
    }
    __syncthreads();

    if (t < NEXP) {
        const int e = t;
        float msum = 0.f; int cnt = 0;
        #pragma unroll 8
        for (int r = 0; r < 64; r++) {
            msum += Ls[r * 65 + e];
            cnt  += (s_eid[r] == e);
        }
        g_me[b * NEXP + e]  = msum;
        g_cnt[b * NEXP + e] = cnt;
    }
}

// ---------------------------------------------------------------------------
// Kernel 3 (R9): scatter with vectorized staging and 4-way-parallel offset
// prefix. 256 threads. Block 0: exp_counts + l_aux.
// ---------------------------------------------------------------------------
__global__ __launch_bounds__(256) void scatter_kernel(float* __restrict__ out)
{
    __shared__ int   sc[NBLK64 * NEXP];   // 32 KB staged counts
    __shared__ int   s_part[4][64];
    __shared__ int   s_e[64];
    __shared__ float s_g[64];
    __shared__ int   cnt0[NEXP];
    __shared__ float s_val[NEXP];

    const int b = blockIdx.x;
    const int t = threadIdx.x;            // 0..255

    // stage counts: 2048 int4 by 256 threads = 8 LDG.128 each (full MLP)
    {
        const int4* g4 = (const int4*)g_cnt;
        int4* s4 = (int4*)sc;
        #pragma unroll
        for (int j = 0; j < 8; j++) s4[t + j * 256] = g4[t + j * 256];
    }
    if (t < 64) {
        s_e[t]  = g_eid[b * 64 + t];
        s_g[t]  = g_gate[b * 64 + t];
        cnt0[t] = 0;
    }
    __syncthreads();

    // 4-way parallel offset prefix: thread (q, tok) sums cnt[q*32 .. ) ∩ [0,b)
    {
        const int tok = t & 63;
        const int q   = t >> 6;           // 0..3
        const int e   = s_e[tok];
        const int lo  = q * 32;
        const int hi  = (b < lo + 32) ? b : (lo + 32);
        int sum = 0;
        #pragma unroll 8
        for (int bp = lo; bp < hi; bp++) sum += sc[bp * NEXP + e];
        s_part[q][tok] = sum;
    }
    __syncthreads();

    // rank + scatter (first two warps; one token each)
    int ee = 0, rank_w = 0, offs = 0; float gg = 0.f; unsigned mm = 0;
    if (t < 64) {
        ee   = s_e[t];
        gg   = s_g[t];
        offs = s_part[0][t] + s_part[1][t] + s_part[2][t] + s_part[3][t];
        mm   = __match_any_sync(0xFFFFFFFFu, ee);
        const int lane = t & 31;
        rank_w = __popc(mm & ((1u << lane) - 1u));
        if (t < 32 && lane == __ffs(mm) - 1) cnt0[ee] = __popc(mm);
    }
    __syncthreads();
    if (t >= 32 && t < 64) rank_w += cnt0[ee];
    if (t < 64) {
        const int rank = offs + rank_w;
        if (rank < CAP) {
            const int s = b * 64 + t;
            size_t base = (size_t)s * (NEXP * CAP) + (size_t)ee * CAP + rank;
            out[1 + base]       = gg;     // combine_weights
            out[1 + SEC + base] = 1.0f;   // dispatch_mask
        }
    }

    // block 0: exp_counts + l_aux from staged counts
    if (b == 0) {
        __syncthreads();
        {
            const int ex = t & 63;
            const int q  = t >> 6;
            int sum = 0;
            #pragma unroll 8
            for (int bp = q * 32; bp < q * 32 + 32; bp++) sum += sc[bp * NEXP + ex];
            s_part[q][ex] = sum;
        }
        __syncthreads();
        if (t < 64) {
            const int run = s_part[0][t] + s_part[1][t] + s_part[2][t] + s_part[3][t];
            float me_tot = 0.f;
            #pragma unroll 8
            for (int bp = 0; bp < NBLK64; bp++) me_tot += g_me[bp * NEXP + t];
            out[1 + 2 * SEC + t] = (float)run;     // exp_counts (pre-drop)
            s_val[t] = me_tot * (float)run;
        }
        __syncthreads();
        if (t == 0) {
            float acc = 0.f;
            for (int k = 0; k < NEXP; k++) acc += s_val[k];
            out[0] = acc * (1.f / 1048576.f);      // E/S^2 = 64/8192^2
        }
    }
}

// ---------------------------------------------------------------------------
extern "C" void kernel_launch(void* const* d_in, const int* in_sizes, int n_in,
                              void* d_out, int out_size)
{
    const float* x  = (const float*)d_in[0];
    const float* wg = (const float*)d_in[1];
    float* out = (float*)d_out;

    gemm_zero_kernel<<<GRID_G, THREADS>>>(x, wg, out);
    gate_kernel<<<NBLK64, 256>>>();
    scatter_kernel<<<NBLK64, 256>>>(out);
}

// round 12
// speedup vs baseline: 3.4603x; 1.4040x over previous
#include <cuda_runtime.h>
#include <cstdint>
#include <math.h>

// Problem constants
#define S_TOK 8192
#define MDIM  4096
#define NEXP  64
#define CAP   128
#define SEC   67108864ULL            // S*E*C
#define OUT_FLOATS 134217793ULL      // 1 + 2*SEC + 64
#define ZMAIN 134217728ULL           // floats zeroed by bulk path (512MB)

// GEMM tiling (R6/R9 proven config)
#define TILE_M 256                   // tokens per CTA
#define KB     16
#define KSPLIT 4
#define KCHUNK (MDIM / KSPLIT)       // 1024
#define NSTEP  (KCHUNK / KB)         // 64
#define NTB    (S_TOK / TILE_M)      // 32 token blocks
#define GRID_G (NTB * KSPLIT)        // 128 CTAs (1 per SM)
#define CTHR   256                   // compute threads (8 warps)
#define THREADS (CTHR + 32)          // + 1 TMA-zero warp
#define LDA 260                      // A smem row stride (floats)
#define LDB 68                       // B smem row stride (floats)

#define ZCHUNK 4096                  // bytes per bulk store
#define ZPC    1024                  // chunks per CTA (128*1024*4KB = 512MB)

#define NBLK64 (S_TOK / 64)          // 128 blocks for gate/scatter

typedef unsigned long long u64;

// ---------- scratch (device globals; fully overwritten each launch) ----------
__device__ float g_part[KSPLIT * S_TOK * NEXP];   // 8 MB partial logits
__device__ int   g_eid[S_TOK];
__device__ float g_gate[S_TOK];
__device__ float g_me[NBLK64 * NEXP];
__device__ int   g_cnt[NBLK64 * NEXP];

// packed f32x2 FMA (PTX-only; ptxas never auto-fuses)
__device__ __forceinline__ void ffma2(u64& d, u64 a, u64 b) {
    asm("fma.rn.f32x2 %0, %1, %2, %0;" : "+l"(d) : "l"(a), "l"(b));
}
__device__ __forceinline__ u64 dup2(float b) {
    u64 r; unsigned u = __float_as_uint(b);
    asm("mov.b64 %0, {%1, %1};" : "=l"(r) : "r"(u));
    return r;
}
__device__ __forceinline__ void barc() {   // compute-warps-only barrier
    asm volatile("bar.sync 1, %0;" :: "n"(CTHR) : "memory");
}
__device__ __forceinline__ uint32_t smem_u32(const void* p) {
    uint32_t a;
    asm("{ .reg .u64 t; cvta.to.shared.u64 t, %1; cvt.u32.u64 %0, t; }"
        : "=r"(a) : "l"(p));
    return a;
}

// ---------------------------------------------------------------------------
// Kernel 1: warps 0-7 = 256x64 fp32 GEMM over a K/4 chunk (R6 shape:
// per-thread 8 tok x 8 exp, 32 FFMA2 / 4 LDS.128 per kk) with EXPLICIT
// register double-buffering of smem loads across kk (hides LDS latency).
// Warp 8 = TMA bulk-zero of the 537MB output (R9 proven engine).
// ---------------------------------------------------------------------------
__global__ __launch_bounds__(THREADS, 1) void gemm_zero_kernel(
    const float* __restrict__ x, const float* __restrict__ wg,
    float* __restrict__ out)
{
    __shared__ float sA[2][KB * LDA];                 // 2 x 16.25 KB
    __shared__ float sB[2][KB * LDB];                 // 2 x 4.25 KB
    __shared__ alignas(16) float4 zbuf[ZCHUNK / 16];  // 4 KB zeros

    const int t  = threadIdx.x;
    const int bx = blockIdx.x;

    {
        const float4 z = make_float4(0.f, 0.f, 0.f, 0.f);
        for (int i = t; i < ZCHUNK / 16; i += THREADS) zbuf[i] = z;
    }
    __syncthreads();

    if (t >= CTHR) {
        // ---------------- TMA zero warp ----------------
        const int zt = t - CTHR;
        if (zt == 0) {
            asm volatile("fence.proxy.async.shared::cta;" ::: "memory");
            const uint32_t zaddr = smem_u32(zbuf);
            char* dst = (char*)out + (size_t)bx * (ZPC * (size_t)ZCHUNK);
            #pragma unroll 4
            for (int c = 0; c < ZPC; c++) {
                asm volatile(
                    "cp.async.bulk.global.shared::cta.bulk_group [%0], [%1], %2;"
                    :: "l"(dst + (size_t)c * ZCHUNK), "r"(zaddr), "r"(ZCHUNK)
                    : "memory");
            }
            asm volatile("cp.async.bulk.commit_group;" ::: "memory");
            asm volatile("cp.async.bulk.wait_group 0;" ::: "memory");
        }
        if (bx == 0) {   // tail: last 65 floats
            for (int i = zt; i < (int)(OUT_FLOATS - ZMAIN); i += 32)
                out[ZMAIN + i] = 0.0f;
        }
        return;
    }

    // ---------------- compute warps (R6 config) ----------------
    const int tb = bx & (NTB - 1);     // token block (0..31)
    const int kh = bx >> 5;            // k chunk (0..3)
    const int w    = t >> 5;           // warp 0..7
    const int lane = t & 31;
    const int tb2  = w >> 1;           // warp token sub-block (0..3): 64 tokens
    const int eb   = w & 1;            // warp expert half (0..1): 32 experts
    const int tg   = lane >> 2;        // token group (0..7): 8 tokens
    const int eg   = lane & 3;         // expert group (0..3): 8 experts
    const int tok0 = tb2 * 64 + tg * 8;
    const int e0   = eb * 32 + eg * 8;

    u64 acc[4][8];                     // 4 token-pairs x 8 experts
    #pragma unroll
    for (int p = 0; p < 4; p++)
        #pragma unroll
        for (int j = 0; j < 8; j++) acc[p][j] = 0ULL;

    const float* xblk = x  + (size_t)tb * TILE_M * MDIM + (size_t)kh * KCHUNK;
    const float* wblk = wg + (size_t)kh * KCHUNK;

    const int arow = t >> 2;           // 0..63
    const int akq  = t & 3;            // 0..3
    const int brow = t >> 2;           // 0..63 (expert)
    const int bkq  = t & 3;            // 0..3

    float4 pa[4]; float4 pb;
    #pragma unroll
    for (int i = 0; i < 4; i++)
        pa[i] = *(const float4*)(xblk + (size_t)(arow + i * 64) * MDIM + akq * 4);
    pb = *(const float4*)(wblk + (size_t)brow * MDIM + bkq * 4);

    // stage step 0
    #pragma unroll
    for (int i = 0; i < 4; i++) {
        const int r = arow + i * 64;
        sA[0][(akq * 4 + 0) * LDA + r] = pa[i].x;
        sA[0][(akq * 4 + 1) * LDA + r] = pa[i].y;
        sA[0][(akq * 4 + 2) * LDA + r] = pa[i].z;
        sA[0][(akq * 4 + 3) * LDA + r] = pa[i].w;
    }
    sB[0][(bkq * 4 + 0) * LDB + brow] = pb.x;
    sB[0][(bkq * 4 + 1) * LDB + brow] = pb.y;
    sB[0][(bkq * 4 + 2) * LDB + brow] = pb.z;
    sB[0][(bkq * 4 + 3) * LDB + brow] = pb.w;
    barc();

    #pragma unroll 1
    for (int s = 0; s < NSTEP; s++) {
        const int cur = s & 1;

        if (s + 1 < NSTEP) {           // global prefetch for next step
            const int k1 = (s + 1) * KB;
            #pragma unroll
            for (int i = 0; i < 4; i++)
                pa[i] = *(const float4*)(xblk + (size_t)(arow + i * 64) * MDIM + k1 + akq * 4);
            pb = *(const float4*)(wblk + (size_t)brow * MDIM + k1 + bkq * 4);
        }

        // inner loop with explicit register double-buffering across kk:
        // load kk+1's smem operands BEFORE issuing kk's 32 FFMA2s.
        {
            ulonglong2 a01 = *(const ulonglong2*)&sA[cur][0 * LDA + tok0];
            ulonglong2 a23 = *(const ulonglong2*)&sA[cur][0 * LDA + tok0 + 4];
            float4 b03 = *(const float4*)&sB[cur][0 * LDB + e0];
            float4 b47 = *(const float4*)&sB[cur][0 * LDB + e0 + 4];
            #pragma unroll
            for (int kk = 0; kk < KB; kk++) {
                ulonglong2 na01, na23; float4 nb03, nb47;
                if (kk + 1 < KB) {
                    const float* ap = &sA[cur][(kk + 1) * LDA + tok0];
                    na01 = *(const ulonglong2*)(ap);
                    na23 = *(const ulonglong2*)(ap + 4);
                    nb03 = *(const float4*)&sB[cur][(kk + 1) * LDB + e0];
                    nb47 = *(const float4*)&sB[cur][(kk + 1) * LDB + e0 + 4];
                }
                u64 ar[4] = { a01.x, a01.y, a23.x, a23.y };
                u64 bd[8] = { dup2(b03.x), dup2(b03.y), dup2(b03.z), dup2(b03.w),
                              dup2(b47.x), dup2(b47.y), dup2(b47.z), dup2(b47.w) };
                #pragma unroll
                for (int p = 0; p < 4; p++)
                    #pragma unroll
                    for (int j = 0; j < 8; j++)
                        ffma2(acc[p][j], ar[p], bd[j]);
                if (kk + 1 < KB) { a01 = na01; a23 = na23; b03 = nb03; b47 = nb47; }
            }
        }

        if (s + 1 < NSTEP) {           // stage next step into other buffer
            const int nxt = cur ^ 1;
            #pragma unroll
            for (int i = 0; i < 4; i++) {
                const int r = arow + i * 64;
                sA[nxt][(akq * 4 + 0) * LDA + r] = pa[i].x;
                sA[nxt][(akq * 4 + 1) * LDA + r] = pa[i].y;
                sA[nxt][(akq * 4 + 2) * LDA + r] = pa[i].z;
                sA[nxt][(akq * 4 + 3) * LDA + r] = pa[i].w;
            }
            sB[nxt][(bkq * 4 + 0) * LDB + brow] = pb.x;
            sB[nxt][(bkq * 4 + 1) * LDB + brow] = pb.y;
            sB[nxt][(bkq * 4 + 2) * LDB + brow] = pb.z;
            sB[nxt][(bkq * 4 + 3) * LDB + brow] = pb.w;
        }
        barc();
    }

    // epilogue: write partial logits [kh][token][expert]
    float* part = g_part + (size_t)kh * S_TOK * NEXP;
    #pragma unroll
    for (int p = 0; p < 4; p++) {
        const size_t t0 = (size_t)tb * TILE_M + tok0 + p * 2;
        float4 lo0, lo1, hi0, hi1;
        lo0.x = __uint_as_float((unsigned)acc[p][0]);
        lo0.y = __uint_as_float((unsigned)acc[p][1]);
        lo0.z = __uint_as_float((unsigned)acc[p][2]);
        lo0.w = __uint_as_float((unsigned)acc[p][3]);
        lo1.x = __uint_as_float((unsigned)acc[p][4]);
        lo1.y = __uint_as_float((unsigned)acc[p][5]);
        lo1.z = __uint_as_float((unsigned)acc[p][6]);
        lo1.w = __uint_as_float((unsigned)acc[p][7]);
        hi0.x = __uint_as_float((unsigned)(acc[p][0] >> 32));
        hi0.y = __uint_as_float((unsigned)(acc[p][1] >> 32));
        hi0.z = __uint_as_float((unsigned)(acc[p][2] >> 32));
        hi0.w = __uint_as_float((unsigned)(acc[p][3] >> 32));
        hi1.x = __uint_as_float((unsigned)(acc[p][4] >> 32));
        hi1.y = __uint_as_float((unsigned)(acc[p][5] >> 32));
        hi1.z = __uint_as_float((unsigned)(acc[p][6] >> 32));
        hi1.w = __uint_as_float((unsigned)(acc[p][7] >> 32));
        *(float4*)&part[t0 * NEXP + e0 + 0]       = lo0;
        *(float4*)&part[t0 * NEXP + e0 + 4]       = lo1;
        *(float4*)&part[(t0 + 1) * NEXP + e0 + 0] = hi0;
        *(float4*)&part[(t0 + 1) * NEXP + e0 + 4] = hi1;
    }
}

// ---------------------------------------------------------------------------
// Kernel 2 (R6): reduce K-split partials, softmax/argmax, per-block me/cnt.
// ---------------------------------------------------------------------------
__global__ __launch_bounds__(256) void gate_kernel()
{
    __shared__ float Ls[64 * 65];
    __shared__ int   s_eid[64];
    const int b = blockIdx.x;        // 0..127
    const int t = threadIdx.x;
    const size_t off = (size_t)b * 64 * NEXP;

    #pragma unroll
    for (int i = 0; i < 4; i++) {
        const int idx4 = t + i * 256;     // 0..1023
        float4 v = *(const float4*)&g_part[off + (size_t)idx4 * 4];
        #pragma unroll
        for (int p = 1; p < KSPLIT; p++) {
            float4 w = *(const float4*)&g_part[(size_t)p * S_TOK * NEXP + off + (size_t)idx4 * 4];
            v.x += w.x; v.y += w.y; v.z += w.z; v.w += w.w;
        }
        const int r = (idx4 * 4) >> 6;
        const int e = (idx4 * 4) & 63;
        Ls[r * 65 + e + 0] = v.x;
        Ls[r * 65 + e + 1] = v.y;
        Ls[r * 65 + e + 2] = v.z;
        Ls[r * 65 + e + 3] = v.w;
    }
    __syncthreads();

    if (t < 64) {
        const int r = t;
        float m = -INFINITY; int am = 0;
        #pragma unroll 8
        for (int e = 0; e < NEXP; e++) {
            float v = Ls[r * 65 + e];
            if (v > m) { m = v; am = e; }
        }
        float sum = 0.f;
        #pragma unroll 8
        for (int e = 0; e < NEXP; e++) {
            float ex = expf(Ls[r * 65 + e] - m);
            Ls[r * 65 + e] = ex;
            sum += ex;
        }
        const float inv = 1.f / sum;
        #pragma unroll 8
        for (int e = 0; e < NEXP; e++) Ls[r * 65 + e] *= inv;
        const int s = b * 64 + r;
        g_eid[s]  = am;
        g_gate[s] = inv;
        s_eid[r]  = am;
    }
    __syncthreads();

    if (t < NEXP) {
        const int e = t;
        float msum = 0.f; int cnt = 0;
        #pragma unroll 8
        for (int r = 0; r < 64; r++) {
            msum += Ls[r * 65 + e];
            cnt  += (s_eid[r] == e);
        }
        g_me[b * NEXP + e]  = msum;
        g_cnt[b * NEXP + e] = cnt;
    }
}

// ---------------------------------------------------------------------------
// Kernel 3 (R9): scatter with vectorized staging and 4-way-parallel offset
// prefix. 256 threads. Block 0: exp_counts + l_aux.
// ---------------------------------------------------------------------------
__global__ __launch_bounds__(256) void scatter_kernel(float* __restrict__ out)
{
    __shared__ int   sc[NBLK64 * NEXP];   // 32 KB staged counts
    __shared__ int   s_part[4][64];
    __shared__ int   s_e[64];
    __shared__ float s_g[64];
    __shared__ int   cnt0[NEXP];
    __shared__ float s_val[NEXP];

    const int b = blockIdx.x;
    const int t = threadIdx.x;            // 0..255

    // stage counts: 2048 int4 by 256 threads = 8 LDG.128 each (full MLP)
    {
        const int4* g4 = (const int4*)g_cnt;
        int4* s4 = (int4*)sc;
        #pragma unroll
        for (int j = 0; j < 8; j++) s4[t + j * 256] = g4[t + j * 256];
    }
    if (t < 64) {
        s_e[t]  = g_eid[b * 64 + t];
        s_g[t]  = g_gate[b * 64 + t];
        cnt0[t] = 0;
    }
    __syncthreads();

    // 4-way parallel offset prefix: thread (q, tok) sums cnt[q*32 .. ) ∩ [0,b)
    {
        const int tok = t & 63;
        const int q   = t >> 6;           // 0..3
        const int e   = s_e[tok];
        const int lo  = q * 32;
        const int hi  = (b < lo + 32) ? b : (lo + 32);
        int sum = 0;
        #pragma unroll 8
        for (int bp = lo; bp < hi; bp++) sum += sc[bp * NEXP + e];
        s_part[q][tok] = sum;
    }
    __syncthreads();

    // rank + scatter (first two warps; one token each)
    int ee = 0, rank_w = 0, offs = 0; float gg = 0.f; unsigned mm = 0;
    if (t < 64) {
        ee   = s_e[t];
        gg   = s_g[t];
        offs = s_part[0][t] + s_part[1][t] + s_part[2][t] + s_part[3][t];
        mm   = __match_any_sync(0xFFFFFFFFu, ee);
        const int lane = t & 31;
        rank_w = __popc(mm & ((1u << lane) - 1u));
        if (t < 32 && lane == __ffs(mm) - 1) cnt0[ee] = __popc(mm);
    }
    __syncthreads();
    if (t >= 32 && t < 64) rank_w += cnt0[ee];
    if (t < 64) {
        const int rank = offs + rank_w;
        if (rank < CAP) {
            const int s = b * 64 + t;
            size_t base = (size_t)s * (NEXP * CAP) + (size_t)ee * CAP + rank;
            out[1 + base]       = gg;     // combine_weights
            out[1 + SEC + base] = 1.0f;   // dispatch_mask
        }
    }

    // block 0: exp_counts + l_aux from staged counts
    if (b == 0) {
        __syncthreads();
        {
            const int ex = t & 63;
            const int q  = t >> 6;
            int sum = 0;
            #pragma unroll 8
            for (int bp = q * 32; bp < q * 32 + 32; bp++) sum += sc[bp * NEXP + ex];
            s_part[q][ex] = sum;
        }
        __syncthreads();
        if (t < 64) {
            const int run = s_part[0][t] + s_part[1][t] + s_part[2][t] + s_part[3][t];
            float me_tot = 0.f;
            #pragma unroll 8
            for (int bp = 0; bp < NBLK64; bp++) me_tot += g_me[bp * NEXP + t];
            out[1 + 2 * SEC + t] = (float)run;     // exp_counts (pre-drop)
            s_val[t] = me_tot * (float)run;
        }
        __syncthreads();
        if (t == 0) {
            float acc = 0.f;
            for (int k = 0; k < NEXP; k++) acc += s_val[k];
            out[0] = acc * (1.f / 1048576.f);      // E/S^2 = 64/8192^2
        }
    }
}

// ---------------------------------------------------------------------------
extern "C" void kernel_launch(void* const* d_in, const int* in_sizes, int n_in,
                              void* d_out, int out_size)
{
    const float* x  = (const float*)d_in[0];
    const float* wg = (const float*)d_in[1];
    float* out = (float*)d_out;

    gemm_zero_kernel<<<GRID_G, THREADS>>>(x, wg, out);
    gate_kernel<<<NBLK64, 256>>>();
    scatter_kernel<<<NBLK64, 256>>>(out);
}